// round 8
// baseline (speedup 1.0000x reference)
#include <cuda_runtime.h>
#include <cuda_fp16.h>
#include <cstdint>

#define SEQ 2048
#define HQ 32
#define HKV 8
#define DH 128
#define SW 1024
#define BM 64
#define BN 64
#define NT 128
// QK_SCALE * log2(e): softmax exp(x) computed as ex2(x) with scale folded into Q
#define QK_SCALE_L2E 0.12754359784919357f
#define L2E 1.4426950408889634f

// smem halves, row stride 136 (272B rows, conflict-free ldmatrix)
#define QSTR 136
#define QB 0                       // 64 x 136 halves = 17408 B
#define KB0 17408
#define VB0 34816
#define KB1 52224
#define VB1 69632
#define SM_TOTAL 87040

__device__ __forceinline__ uint32_t smem_u32(const void* p) {
    uint32_t a;
    asm("{ .reg .u64 t; cvta.to.shared.u64 t, %1; cvt.u32.u64 %0, t; }" : "=r"(a) : "l"(p));
    return a;
}
__device__ __forceinline__ void ldsm_x4(uint32_t* r, uint32_t a) {
    asm volatile("ldmatrix.sync.aligned.m8n8.x4.shared.b16 {%0,%1,%2,%3}, [%4];"
                 : "=r"(r[0]), "=r"(r[1]), "=r"(r[2]), "=r"(r[3]) : "r"(a));
}
__device__ __forceinline__ void ldsm_x4_t(uint32_t* r, uint32_t a) {
    asm volatile("ldmatrix.sync.aligned.m8n8.x4.trans.shared.b16 {%0,%1,%2,%3}, [%4];"
                 : "=r"(r[0]), "=r"(r[1]), "=r"(r[2]), "=r"(r[3]) : "r"(a));
}
__device__ __forceinline__ void mma16816(float* c, const uint32_t* a, uint32_t b0, uint32_t b1) {
    asm volatile("mma.sync.aligned.m16n8k16.row.col.f32.f16.f16.f32 "
                 "{%0,%1,%2,%3}, {%4,%5,%6,%7}, {%8,%9}, {%0,%1,%2,%3};"
                 : "+f"(c[0]), "+f"(c[1]), "+f"(c[2]), "+f"(c[3])
                 : "r"(a[0]), "r"(a[1]), "r"(a[2]), "r"(a[3]), "r"(b0), "r"(b1));
}
__device__ __forceinline__ uint32_t h2u(float x, float y) {
    __half2 h = __floats2half2_rn(x, y);
    return *reinterpret_cast<uint32_t*>(&h);
}
__device__ __forceinline__ float ex2(float x) {
    float y;
    asm("ex2.approx.f32 %0, %1;" : "=f"(y) : "f"(x));
    return y;
}

__global__ void __launch_bounds__(NT, 2)
attn_hmma(const float* __restrict__ gq, const float* __restrict__ gk,
          const float* __restrict__ gv, const float* __restrict__ gsink,
          float* __restrict__ gout)
{
    extern __shared__ __half smh[];
    const uint32_t sb = smem_u32(smh);
    const int tid = threadIdx.x;
    const int w   = tid >> 5;
    const int l   = tid & 31;
    const int h   = blockIdx.y;
    const int hkv = h >> 2;
    const int qi0 = blockIdx.x * BM;

    // ---- load Q tile [64x128] (scale*log2e, fp32->fp16) ----
#pragma unroll
    for (int i = 0; i < 16; i++) {
        int slot = tid + i * NT;
        int r = slot >> 5, c4 = slot & 31;
        float4 t = *reinterpret_cast<const float4*>(
            &gq[((size_t)(qi0 + r) * HQ + h) * DH + c4 * 4]);
        uint2 u;
        u.x = h2u(t.x * QK_SCALE_L2E, t.y * QK_SCALE_L2E);
        u.y = h2u(t.z * QK_SCALE_L2E, t.w * QK_SCALE_L2E);
        *reinterpret_cast<uint2*>(&smh[r * QSTR + c4 * 4]) = u;
    }

    int j_lo = (qi0 >= SW) ? (qi0 - SW) : 0;   // 64-aligned window start

    // ---- prologue: load K/V tile 0 into buffer 0 ----
#pragma unroll
    for (int i = 0; i < 16; i++) {
        int slot = tid + i * NT;
        int r = slot >> 5, c4 = slot & 31;
        size_t base = ((size_t)(j_lo + r) * HKV + hkv) * DH + c4 * 4;
        float4 kt = *reinterpret_cast<const float4*>(&gk[base]);
        float4 vt = *reinterpret_cast<const float4*>(&gv[base]);
        uint2 ku, vu;
        ku.x = h2u(kt.x, kt.y); ku.y = h2u(kt.z, kt.w);
        vu.x = h2u(vt.x, vt.y); vu.y = h2u(vt.z, vt.w);
        int off = r * QSTR + c4 * 4;
        *reinterpret_cast<uint2*>(&smh[KB0 / 2 + off]) = ku;
        *reinterpret_cast<uint2*>(&smh[VB0 / 2 + off]) = vu;
    }
    __syncthreads();

    // ---- preload Q fragments (constant across all key tiles) ----
    uint32_t qf[8][4];
    {
        int row = 16 * w + (l & 15);
#pragma unroll
        for (int ks = 0; ks < 8; ks++) {
            uint32_t a = sb + QB + (uint32_t)(row * QSTR + ks * 16 + ((l >> 4) << 3)) * 2;
            ldsm_x4(qf[ks], a);
        }
    }

    float o[16][4];
#pragma unroll
    for (int i = 0; i < 16; i++)
#pragma unroll
        for (int j = 0; j < 4; j++) o[i][j] = 0.0f;
    float lsum0 = 0.0f, lsum1 = 0.0f;

    const int wrow0 = qi0 + 16 * w;
    const int wrow1 = wrow0 + 15;
    const int cb  = (l & 3) * 2;
    const int r0g = wrow0 + (l >> 2);

    const int kbrow = ((l >> 4) & 1) * 8 + (l & 7);
    const int kbcol = ((l >> 3) & 1) * 8;
    const int vbrow = ((l >> 3) & 1) * 8 + (l & 7);
    const int vbcol = ((l >> 4) & 1) * 8;

    int t = 0;
    for (int j0 = j_lo; j0 < qi0 + BM; j0 += BN, t++) {
        const uint32_t kb = sb + ((t & 1) ? KB1 : KB0);
        const uint32_t vb = sb + ((t & 1) ? VB1 : VB0);

        // ---- compute tile t (per-warp skip) ----
        bool live = !(j0 > wrow1) && !(j0 + BN - 1 < wrow0 - (SW - 1));
        if (live) {
            const bool full = (j0 + BN - 1 <= wrow0) && (wrow1 - j0 < SW);

            float sc[8][4];
#pragma unroll
            for (int i = 0; i < 8; i++)
#pragma unroll
                for (int j = 0; j < 4; j++) sc[i][j] = 0.0f;

#pragma unroll
            for (int ks = 0; ks < 8; ks++) {
#pragma unroll
                for (int np = 0; np < 4; np++) {
                    uint32_t b[4];
                    uint32_t a = kb +
                        (uint32_t)((np * 16 + kbrow) * QSTR + ks * 16 + kbcol) * 2;
                    ldsm_x4(b, a);
                    mma16816(sc[2 * np],     qf[ks], b[0], b[1]);
                    mma16816(sc[2 * np + 1], qf[ks], b[2], b[3]);
                }
            }

            uint32_t pe[8][2];
            if (full) {
#pragma unroll
                for (int np = 0; np < 8; np++) {
                    float e0 = ex2(sc[np][0]), e1 = ex2(sc[np][1]);
                    float e2 = ex2(sc[np][2]), e3 = ex2(sc[np][3]);
                    lsum0 += e0 + e1; lsum1 += e2 + e3;
                    pe[np][0] = h2u(e0, e1); pe[np][1] = h2u(e2, e3);
                }
            } else {
#pragma unroll
                for (int np = 0; np < 8; np++) {
                    int j = j0 + np * 8 + cb;
                    bool o0 = (j     <= r0g)     && (r0g - j     < SW);
                    bool o1 = (j + 1 <= r0g)     && (r0g - j - 1 < SW);
                    bool o2 = (j     <= r0g + 8) && (r0g + 8 - j < SW);
                    bool o3 = (j + 1 <= r0g + 8) && (r0g + 7 - j < SW);
                    float e0 = o0 ? ex2(sc[np][0]) : 0.0f;
                    float e1 = o1 ? ex2(sc[np][1]) : 0.0f;
                    float e2 = o2 ? ex2(sc[np][2]) : 0.0f;
                    float e3 = o3 ? ex2(sc[np][3]) : 0.0f;
                    lsum0 += e0 + e1; lsum1 += e2 + e3;
                    pe[np][0] = h2u(e0, e1); pe[np][1] = h2u(e2, e3);
                }
            }

#pragma unroll
            for (int kc = 0; kc < 4; kc++) {
                uint32_t a[4];
                a[0] = pe[2 * kc][0];     a[1] = pe[2 * kc][1];
                a[2] = pe[2 * kc + 1][0]; a[3] = pe[2 * kc + 1][1];
#pragma unroll
                for (int dn = 0; dn < 8; dn++) {
                    uint32_t b[4];
                    uint32_t ad = vb +
                        (uint32_t)((kc * 16 + vbrow) * QSTR + dn * 16 + vbcol) * 2;
                    ldsm_x4_t(b, ad);
                    mma16816(o[2 * dn],     a, b[0], b[1]);
                    mma16816(o[2 * dn + 1], a, b[2], b[3]);
                }
            }
        }

        // ---- load tile t+1 into the other buffer ----
        int jn = j0 + BN;
        if (jn < qi0 + BM) {
            int kbn = (t & 1) ? KB0 : KB1;
            int vbn = (t & 1) ? VB0 : VB1;
#pragma unroll
            for (int i = 0; i < 16; i++) {
                int slot = tid + i * NT;
                int r = slot >> 5, c4 = slot & 31;
                size_t base = ((size_t)(jn + r) * HKV + hkv) * DH + c4 * 4;
                float4 kt = *reinterpret_cast<const float4*>(&gk[base]);
                float4 vt = *reinterpret_cast<const float4*>(&gv[base]);
                uint2 ku, vu;
                ku.x = h2u(kt.x, kt.y); ku.y = h2u(kt.z, kt.w);
                vu.x = h2u(vt.x, vt.y); vu.y = h2u(vt.z, vt.w);
                int off = r * QSTR + c4 * 4;
                *reinterpret_cast<uint2*>(&smh[kbn / 2 + off]) = ku;
                *reinterpret_cast<uint2*>(&smh[vbn / 2 + off]) = vu;
            }
        }
        __syncthreads();
    }

    // ---- epilogue: row-sum reduce, add sink, normalize, store ----
    lsum0 += __shfl_xor_sync(0xFFFFFFFF, lsum0, 1);
    lsum0 += __shfl_xor_sync(0xFFFFFFFF, lsum0, 2);
    lsum1 += __shfl_xor_sync(0xFFFFFFFF, lsum1, 1);
    lsum1 += __shfl_xor_sync(0xFFFFFFFF, lsum1, 2);
    const float sexp = ex2(gsink[h] * L2E);
    const float inv0 = 1.0f / (lsum0 + sexp);
    const float inv1 = 1.0f / (lsum1 + sexp);

    const size_t ob0 = ((size_t)r0g * HQ + h) * DH;
    const size_t ob1 = ((size_t)(r0g + 8) * HQ + h) * DH;
#pragma unroll
    for (int nc = 0; nc < 16; nc++) {
        int d0 = nc * 8 + cb;
        float2 v0 = make_float2(o[nc][0] * inv0, o[nc][1] * inv0);
        float2 v1 = make_float2(o[nc][2] * inv1, o[nc][3] * inv1);
        *reinterpret_cast<float2*>(&gout[ob0 + d0]) = v0;
        *reinterpret_cast<float2*>(&gout[ob1 + d0]) = v1;
    }
}

extern "C" void kernel_launch(void* const* d_in, const int* in_sizes, int n_in,
                              void* d_out, int out_size)
{
    const float* q    = (const float*)d_in[0];
    const float* k    = (const float*)d_in[1];
    const float* v    = (const float*)d_in[2];
    const float* sink = (const float*)d_in[3];
    // d_in[4] cache_state, d_in[5] seq_block_ids: dead inputs (reference discards the write)
    float* out = (float*)d_out;

    cudaFuncSetAttribute(attn_hmma, cudaFuncAttributeMaxDynamicSharedMemorySize, SM_TOTAL);
    dim3 grid(SEQ / BM, HQ);
    attn_hmma<<<grid, NT, SM_TOTAL>>>(q, k, v, sink, out);
}

// round 9
// speedup vs baseline: 1.1998x; 1.1998x over previous
#include <cuda_runtime.h>
#include <cuda_fp16.h>
#include <cstdint>

#define SEQ 2048
#define HQ 32
#define HKV 8
#define DH 128
#define SW 1024
#define BM 128
#define BN 64
#define NT 256
#define QK_SCALE_L2E 0.12754359784919357f  // (1/sqrt(128)) * log2(e)
#define L2E 1.4426950408889634f

// row stride 136 halves (272B = 17*16B: 16B-aligned rows, conflict-free ldmatrix)
#define QSTR 136
#define ROWB 272
#define QB 0                        // 128 x 272B = 34816
#define KB0 34816                   // 64 x 272B  = 17408
#define VB0 52224
#define KB1 69632
#define VB1 87040
#define SM_TOTAL 104448
#define TILEB 17408
#define TILE_CHUNKS 1088            // 17408 / 16

// fp16 K/V scratch in smem-image layout: [hkv][s][136] halves
__device__ __align__(16) __half g_kh[HKV * SEQ * QSTR];
__device__ __align__(16) __half g_vh[HKV * SEQ * QSTR];

__device__ __forceinline__ uint32_t smem_u32(const void* p) {
    uint32_t a;
    asm("{ .reg .u64 t; cvta.to.shared.u64 t, %1; cvt.u32.u64 %0, t; }" : "=r"(a) : "l"(p));
    return a;
}
__device__ __forceinline__ void ldsm_x4(uint32_t* r, uint32_t a) {
    asm volatile("ldmatrix.sync.aligned.m8n8.x4.shared.b16 {%0,%1,%2,%3}, [%4];"
                 : "=r"(r[0]), "=r"(r[1]), "=r"(r[2]), "=r"(r[3]) : "r"(a));
}
__device__ __forceinline__ void ldsm_x4_t(uint32_t* r, uint32_t a) {
    asm volatile("ldmatrix.sync.aligned.m8n8.x4.trans.shared.b16 {%0,%1,%2,%3}, [%4];"
                 : "=r"(r[0]), "=r"(r[1]), "=r"(r[2]), "=r"(r[3]) : "r"(a));
}
__device__ __forceinline__ void mma16816(float* c, const uint32_t* a, uint32_t b0, uint32_t b1) {
    asm volatile("mma.sync.aligned.m16n8k16.row.col.f32.f16.f16.f32 "
                 "{%0,%1,%2,%3}, {%4,%5,%6,%7}, {%8,%9}, {%0,%1,%2,%3};"
                 : "+f"(c[0]), "+f"(c[1]), "+f"(c[2]), "+f"(c[3])
                 : "r"(a[0]), "r"(a[1]), "r"(a[2]), "r"(a[3]), "r"(b0), "r"(b1));
}
__device__ __forceinline__ uint32_t h2u(float x, float y) {
    __half2 h = __floats2half2_rn(x, y);
    return *reinterpret_cast<uint32_t*>(&h);
}
__device__ __forceinline__ float ex2(float x) {
    float y;
    asm("ex2.approx.f32 %0, %1;" : "=f"(y) : "f"(x));
    return y;
}
__device__ __forceinline__ void cp16(uint32_t s, const __half* g) {
    asm volatile("cp.async.cg.shared.global [%0], [%1], 16;"
                 :: "r"(s), "l"(__cvta_generic_to_global(g)) : "memory");
}
#define CP_COMMIT() asm volatile("cp.async.commit_group;" ::: "memory")
#define CP_WAIT1()  asm volatile("cp.async.wait_group 1;" ::: "memory")

// ---- preprocess: K/V fp32 [S][HKV][128] -> fp16 [hkv][s][136] ----
__global__ void __launch_bounds__(256)
cvt_kv(const float* __restrict__ gk, const float* __restrict__ gv)
{
    int idx = blockIdx.x * 256 + threadIdx.x;      // 2048*8*32 threads
    int d4  = idx & 31;
    int hkv = (idx >> 5) & 7;
    int s   = idx >> 8;
    size_t gi = (((size_t)s * HKV) + hkv) * DH + d4 * 4;
    float4 kt = *reinterpret_cast<const float4*>(&gk[gi]);
    float4 vt = *reinterpret_cast<const float4*>(&gv[gi]);
    uint2 ku, vu;
    ku.x = h2u(kt.x, kt.y); ku.y = h2u(kt.z, kt.w);
    vu.x = h2u(vt.x, vt.y); vu.y = h2u(vt.z, vt.w);
    size_t o = ((size_t)hkv * SEQ + s) * QSTR + d4 * 4;
    *reinterpret_cast<uint2*>(&g_kh[o]) = ku;
    *reinterpret_cast<uint2*>(&g_vh[o]) = vu;
}

__device__ __forceinline__ void issue_tile(uint32_t sb, int buf, int hkv, int j0, int tid) {
    const __half* kg = &g_kh[((size_t)hkv * SEQ + j0) * QSTR];
    const __half* vg = &g_vh[((size_t)hkv * SEQ + j0) * QSTR];
    uint32_t kd = sb + (buf ? KB1 : KB0);
    uint32_t vd = sb + (buf ? VB1 : VB0);
#pragma unroll
    for (int i = 0; i < 5; i++) {
        int c = tid + i * NT;
        if (c < TILE_CHUNKS) {
            cp16(kd + c * 16, kg + c * 8);
            cp16(vd + c * 16, vg + c * 8);
        }
    }
}

__global__ void __launch_bounds__(NT, 1)
attn_hmma(const float* __restrict__ gq, const float* __restrict__ gsink,
          float* __restrict__ gout)
{
    extern __shared__ __half smh[];
    const uint32_t sb = smem_u32(smh);
    const int tid = threadIdx.x;
    const int w   = tid >> 5;
    const int l   = tid & 31;
    const int h   = blockIdx.y;
    const int hkv = h >> 2;
    const int qi0 = blockIdx.x * BM;
    const int qend = qi0 + BM;

    int j_lo = (qi0 >= SW) ? (qi0 - SW) : 0;   // 64-aligned window start

    // prologue: prefetch tiles 0 and 1
    issue_tile(sb, 0, hkv, j_lo, tid);
    CP_COMMIT();
    if (j_lo + BN < qend) issue_tile(sb, 1, hkv, j_lo + BN, tid);
    CP_COMMIT();

    // ---- load Q tile [128x128] (scale*log2e, fp32->fp16) ----
#pragma unroll
    for (int i = 0; i < 16; i++) {
        int slot = tid + i * NT;
        int r = slot >> 5, c4 = slot & 31;
        float4 t = *reinterpret_cast<const float4*>(
            &gq[((size_t)(qi0 + r) * HQ + h) * DH + c4 * 4]);
        uint2 u;
        u.x = h2u(t.x * QK_SCALE_L2E, t.y * QK_SCALE_L2E);
        u.y = h2u(t.z * QK_SCALE_L2E, t.w * QK_SCALE_L2E);
        *reinterpret_cast<uint2*>(&smh[r * QSTR + c4 * 4]) = u;
    }
    CP_WAIT1();           // tile 0 resident
    __syncthreads();

    // ---- preload Q fragments ----
    uint32_t qf[8][4];
    {
        int row = 16 * w + (l & 15);
#pragma unroll
        for (int ks = 0; ks < 8; ks++) {
            uint32_t a = sb + QB + (uint32_t)(row * QSTR + ks * 16 + ((l >> 4) << 3)) * 2;
            ldsm_x4(qf[ks], a);
        }
    }

    float o[16][4];
#pragma unroll
    for (int i = 0; i < 16; i++)
#pragma unroll
        for (int j = 0; j < 4; j++) o[i][j] = 0.0f;
    float lsum0 = 0.0f, lsum1 = 0.0f;

    const int wrow0 = qi0 + 16 * w;
    const int wrow1 = wrow0 + 15;
    const int cb  = (l & 3) * 2;
    const int r0g = wrow0 + (l >> 2);

    const int kbrow = ((l >> 4) & 1) * 8 + (l & 7);
    const int kbcol = ((l >> 3) & 1) * 8;
    const int vbrow = ((l >> 3) & 1) * 8 + (l & 7);
    const int vbcol = ((l >> 4) & 1) * 8;

    int t = 0;
    for (int j0 = j_lo; j0 < qend; j0 += BN, t++) {
        const uint32_t kb = sb + ((t & 1) ? KB1 : KB0);
        const uint32_t vb = sb + ((t & 1) ? VB1 : VB0);

        bool live = !(j0 > wrow1) && !(j0 + BN - 1 < wrow0 - (SW - 1));
        if (live) {
            const bool full = (j0 + BN - 1 <= wrow0) && (wrow1 - j0 < SW);

            float sc[8][4];
#pragma unroll
            for (int i = 0; i < 8; i++)
#pragma unroll
                for (int j = 0; j < 4; j++) sc[i][j] = 0.0f;

#pragma unroll
            for (int ks = 0; ks < 8; ks++) {
#pragma unroll
                for (int np = 0; np < 4; np++) {
                    uint32_t b[4];
                    uint32_t a = kb +
                        (uint32_t)((np * 16 + kbrow) * QSTR + ks * 16 + kbcol) * 2;
                    ldsm_x4(b, a);
                    mma16816(sc[2 * np],     qf[ks], b[0], b[1]);
                    mma16816(sc[2 * np + 1], qf[ks], b[2], b[3]);
                }
            }

            uint32_t pe[8][2];
            if (full) {
#pragma unroll
                for (int np = 0; np < 8; np++) {
                    float e0 = ex2(sc[np][0]), e1 = ex2(sc[np][1]);
                    float e2 = ex2(sc[np][2]), e3 = ex2(sc[np][3]);
                    lsum0 += e0 + e1; lsum1 += e2 + e3;
                    pe[np][0] = h2u(e0, e1); pe[np][1] = h2u(e2, e3);
                }
            } else {
#pragma unroll
                for (int np = 0; np < 8; np++) {
                    int j = j0 + np * 8 + cb;
                    bool o0 = (j     <= r0g)     && (r0g - j     < SW);
                    bool o1 = (j + 1 <= r0g)     && (r0g - j - 1 < SW);
                    bool o2 = (j     <= r0g + 8) && (r0g + 8 - j < SW);
                    bool o3 = (j + 1 <= r0g + 8) && (r0g + 7 - j < SW);
                    float e0 = o0 ? ex2(sc[np][0]) : 0.0f;
                    float e1 = o1 ? ex2(sc[np][1]) : 0.0f;
                    float e2 = o2 ? ex2(sc[np][2]) : 0.0f;
                    float e3 = o3 ? ex2(sc[np][3]) : 0.0f;
                    lsum0 += e0 + e1; lsum1 += e2 + e3;
                    pe[np][0] = h2u(e0, e1); pe[np][1] = h2u(e2, e3);
                }
            }

#pragma unroll
            for (int kc = 0; kc < 4; kc++) {
                uint32_t a[4];
                a[0] = pe[2 * kc][0];     a[1] = pe[2 * kc][1];
                a[2] = pe[2 * kc + 1][0]; a[3] = pe[2 * kc + 1][1];
#pragma unroll
                for (int dn = 0; dn < 8; dn++) {
                    uint32_t b[4];
                    uint32_t ad = vb +
                        (uint32_t)((kc * 16 + vbrow) * QSTR + dn * 16 + vbcol) * 2;
                    ldsm_x4_t(b, ad);
                    mma16816(o[2 * dn],     a, b[0], b[1]);
                    mma16816(o[2 * dn + 1], a, b[2], b[3]);
                }
            }
        }

        __syncthreads();                       // everyone done reading buf[t&1]
        int jn2 = j0 + 2 * BN;
        if (jn2 < qend) issue_tile(sb, t & 1, hkv, jn2, tid);
        CP_COMMIT();                           // one group per iter (may be empty)
        CP_WAIT1();                            // tile t+1 resident
        __syncthreads();
    }

    // ---- epilogue ----
    lsum0 += __shfl_xor_sync(0xFFFFFFFF, lsum0, 1);
    lsum0 += __shfl_xor_sync(0xFFFFFFFF, lsum0, 2);
    lsum1 += __shfl_xor_sync(0xFFFFFFFF, lsum1, 1);
    lsum1 += __shfl_xor_sync(0xFFFFFFFF, lsum1, 2);
    const float sexp = ex2(gsink[h] * L2E);
    const float inv0 = 1.0f / (lsum0 + sexp);
    const float inv1 = 1.0f / (lsum1 + sexp);

    const size_t ob0 = ((size_t)r0g * HQ + h) * DH;
    const size_t ob1 = ((size_t)(r0g + 8) * HQ + h) * DH;
#pragma unroll
    for (int nc = 0; nc < 16; nc++) {
        int d0 = nc * 8 + cb;
        float2 v0 = make_float2(o[nc][0] * inv0, o[nc][1] * inv0);
        float2 v1 = make_float2(o[nc][2] * inv1, o[nc][3] * inv1);
        *reinterpret_cast<float2*>(&gout[ob0 + d0]) = v0;
        *reinterpret_cast<float2*>(&gout[ob1 + d0]) = v1;
    }
}

extern "C" void kernel_launch(void* const* d_in, const int* in_sizes, int n_in,
                              void* d_out, int out_size)
{
    const float* q    = (const float*)d_in[0];
    const float* k    = (const float*)d_in[1];
    const float* v    = (const float*)d_in[2];
    const float* sink = (const float*)d_in[3];
    // d_in[4] cache_state, d_in[5] seq_block_ids: dead inputs (reference discards the write)
    float* out = (float*)d_out;

    cvt_kv<<<SEQ * HKV * 32 / 256, 256>>>(k, v);

    cudaFuncSetAttribute(attn_hmma, cudaFuncAttributeMaxDynamicSharedMemorySize, SM_TOTAL);
    dim3 grid(SEQ / BM, HQ);
    attn_hmma<<<grid, NT, SM_TOTAL>>>(q, sink, out);
}

// round 10
// speedup vs baseline: 1.2132x; 1.0111x over previous
#include <cuda_runtime.h>
#include <cuda_fp16.h>
#include <cstdint>

#define SEQ 2048
#define HQ 32
#define HKV 8
#define DH 128
#define SW 1024
#define BM 128
#define BN 64
#define NT 256
#define QK_SCALE_L2E 0.12754359784919357f  // (1/sqrt(128)) * log2(e)
#define L2E 1.4426950408889634f

// row stride 136 halves (272B = 17*16B: 16B-aligned rows, conflict-free ldmatrix)
#define QSTR 136
#define QB 0                        // 128 x 272B = 34816
#define KB0 34816                   // 64 x 272B  = 17408
#define VB0 52224
#define KB1 69632
#define VB1 87040
#define SM_TOTAL 104448
#define TILE_CHUNKS 1088            // 17408 / 16

// fp16 K/V scratch in smem-image layout: [hkv][s][136] halves
__device__ __align__(16) __half g_kh[HKV * SEQ * QSTR];
__device__ __align__(16) __half g_vh[HKV * SEQ * QSTR];

__device__ __forceinline__ uint32_t smem_u32(const void* p) {
    uint32_t a;
    asm("{ .reg .u64 t; cvta.to.shared.u64 t, %1; cvt.u32.u64 %0, t; }" : "=r"(a) : "l"(p));
    return a;
}
__device__ __forceinline__ void ldsm_x4(uint32_t* r, uint32_t a) {
    asm volatile("ldmatrix.sync.aligned.m8n8.x4.shared.b16 {%0,%1,%2,%3}, [%4];"
                 : "=r"(r[0]), "=r"(r[1]), "=r"(r[2]), "=r"(r[3]) : "r"(a));
}
__device__ __forceinline__ void ldsm_x4_t(uint32_t* r, uint32_t a) {
    asm volatile("ldmatrix.sync.aligned.m8n8.x4.trans.shared.b16 {%0,%1,%2,%3}, [%4];"
                 : "=r"(r[0]), "=r"(r[1]), "=r"(r[2]), "=r"(r[3]) : "r"(a));
}
__device__ __forceinline__ void mma16816(float* c, const uint32_t* a, uint32_t b0, uint32_t b1) {
    asm volatile("mma.sync.aligned.m16n8k16.row.col.f32.f16.f16.f32 "
                 "{%0,%1,%2,%3}, {%4,%5,%6,%7}, {%8,%9}, {%0,%1,%2,%3};"
                 : "+f"(c[0]), "+f"(c[1]), "+f"(c[2]), "+f"(c[3])
                 : "r"(a[0]), "r"(a[1]), "r"(a[2]), "r"(a[3]), "r"(b0), "r"(b1));
}
__device__ __forceinline__ uint32_t h2u(float x, float y) {
    __half2 h = __floats2half2_rn(x, y);
    return *reinterpret_cast<uint32_t*>(&h);
}
__device__ __forceinline__ float ex2(float x) {
    float y;
    asm("ex2.approx.f32 %0, %1;" : "=f"(y) : "f"(x));
    return y;
}
__device__ __forceinline__ void cp16(uint32_t s, const __half* g) {
    asm volatile("cp.async.cg.shared.global [%0], [%1], 16;"
                 :: "r"(s), "l"(__cvta_generic_to_global(g)) : "memory");
}
#define CP_COMMIT() asm volatile("cp.async.commit_group;" ::: "memory")
#define CP_WAIT1()  asm volatile("cp.async.wait_group 1;" ::: "memory")

// ---- preprocess: K/V fp32 [S][HKV][128] -> fp16 [hkv][s][136] ----
__global__ void __launch_bounds__(256)
cvt_kv(const float* __restrict__ gk, const float* __restrict__ gv)
{
    int idx = blockIdx.x * 256 + threadIdx.x;
    int d4  = idx & 31;
    int hkv = (idx >> 5) & 7;
    int s   = idx >> 8;
    size_t gi = (((size_t)s * HKV) + hkv) * DH + d4 * 4;
    float4 kt = *reinterpret_cast<const float4*>(&gk[gi]);
    float4 vt = *reinterpret_cast<const float4*>(&gv[gi]);
    uint2 ku, vu;
    ku.x = h2u(kt.x, kt.y); ku.y = h2u(kt.z, kt.w);
    vu.x = h2u(vt.x, vt.y); vu.y = h2u(vt.z, vt.w);
    size_t o = ((size_t)hkv * SEQ + s) * QSTR + d4 * 4;
    *reinterpret_cast<uint2*>(&g_kh[o]) = ku;
    *reinterpret_cast<uint2*>(&g_vh[o]) = vu;
}

__device__ __forceinline__ void issue_tile(uint32_t sb, int buf, int hkv, int j0, int tid) {
    const __half* kg = &g_kh[((size_t)hkv * SEQ + j0) * QSTR];
    const __half* vg = &g_vh[((size_t)hkv * SEQ + j0) * QSTR];
    uint32_t kd = sb + (buf ? KB1 : KB0);
    uint32_t vd = sb + (buf ? VB1 : VB0);
#pragma unroll
    for (int i = 0; i < 5; i++) {
        int c = tid + i * NT;
        if (c < TILE_CHUNKS) {
            cp16(kd + c * 16, kg + c * 8);
            cp16(vd + c * 16, vg + c * 8);
        }
    }
}

__global__ void __launch_bounds__(NT, 2)
attn_hmma(const float* __restrict__ gq, const float* __restrict__ gsink,
          float* __restrict__ gout)
{
    extern __shared__ __half smh[];
    const uint32_t sb = smem_u32(smh);
    const int tid = threadIdx.x;
    const int w   = tid >> 5;
    const int l   = tid & 31;
    const int h   = blockIdx.y;
    const int hkv = h >> 2;
    const int qi0 = blockIdx.x * BM;
    const int qend = qi0 + BM;

    int j_lo = (qi0 >= SW) ? (qi0 - SW) : 0;   // 64-aligned window start

    // prologue: prefetch tiles 0 and 1
    issue_tile(sb, 0, hkv, j_lo, tid);
    CP_COMMIT();
    if (j_lo + BN < qend) issue_tile(sb, 1, hkv, j_lo + BN, tid);
    CP_COMMIT();

    // ---- load Q tile [128x128] (scale*log2e, fp32->fp16) ----
#pragma unroll
    for (int i = 0; i < 16; i++) {
        int slot = tid + i * NT;
        int r = slot >> 5, c4 = slot & 31;
        float4 t = *reinterpret_cast<const float4*>(
            &gq[((size_t)(qi0 + r) * HQ + h) * DH + c4 * 4]);
        uint2 u;
        u.x = h2u(t.x * QK_SCALE_L2E, t.y * QK_SCALE_L2E);
        u.y = h2u(t.z * QK_SCALE_L2E, t.w * QK_SCALE_L2E);
        *reinterpret_cast<uint2*>(&smh[r * QSTR + c4 * 4]) = u;
    }
    CP_WAIT1();           // tile 0 resident
    __syncthreads();

    // ---- preload Q fragments (register-resident all tiles) ----
    uint32_t qf[8][4];
    {
        int row = 16 * w + (l & 15);
#pragma unroll
        for (int ks = 0; ks < 8; ks++) {
            uint32_t a = sb + QB + (uint32_t)(row * QSTR + ks * 16 + ((l >> 4) << 3)) * 2;
            ldsm_x4(qf[ks], a);
        }
    }

    float o[16][4];
#pragma unroll
    for (int i = 0; i < 16; i++)
#pragma unroll
        for (int j = 0; j < 4; j++) o[i][j] = 0.0f;
    float lsum0 = 0.0f, lsum1 = 0.0f;

    const int wrow0 = qi0 + 16 * w;
    const int wrow1 = wrow0 + 15;
    const int cb  = (l & 3) * 2;
    const int r0g = wrow0 + (l >> 2);

    const int kbrow = ((l >> 4) & 1) * 8 + (l & 7);
    const int kbcol = ((l >> 3) & 1) * 8;
    const int vbrow = ((l >> 3) & 1) * 8 + (l & 7);
    const int vbcol = ((l >> 4) & 1) * 8;

    int t = 0;
    for (int j0 = j_lo; j0 < qend; j0 += BN, t++) {
        const uint32_t kb = sb + ((t & 1) ? KB1 : KB0);
        const uint32_t vb = sb + ((t & 1) ? VB1 : VB0);

        bool live = !(j0 > wrow1) && !(j0 + BN - 1 < wrow0 - (SW - 1));
        if (live) {
            const bool full = (j0 + BN - 1 <= wrow0) && (wrow1 - j0 < SW);

            // ---- fused 16-key strips: QK -> exp -> PV ----
#pragma unroll
            for (int kc = 0; kc < 4; kc++) {
                float sc[2][4];
#pragma unroll
                for (int i = 0; i < 2; i++)
#pragma unroll
                    for (int j = 0; j < 4; j++) sc[i][j] = 0.0f;

#pragma unroll
                for (int ks = 0; ks < 8; ks++) {
                    uint32_t b[4];
                    uint32_t a = kb +
                        (uint32_t)((kc * 16 + kbrow) * QSTR + ks * 16 + kbcol) * 2;
                    ldsm_x4(b, a);
                    mma16816(sc[0], qf[ks], b[0], b[1]);
                    mma16816(sc[1], qf[ks], b[2], b[3]);
                }

                uint32_t pe[4];
                if (full) {
                    float e0 = ex2(sc[0][0]), e1 = ex2(sc[0][1]);
                    float e2 = ex2(sc[0][2]), e3 = ex2(sc[0][3]);
                    float f0 = ex2(sc[1][0]), f1 = ex2(sc[1][1]);
                    float f2 = ex2(sc[1][2]), f3 = ex2(sc[1][3]);
                    lsum0 += e0 + e1 + f0 + f1;
                    lsum1 += e2 + e3 + f2 + f3;
                    pe[0] = h2u(e0, e1); pe[1] = h2u(e2, e3);
                    pe[2] = h2u(f0, f1); pe[3] = h2u(f2, f3);
                } else {
#pragma unroll
                    for (int half = 0; half < 2; half++) {
                        int j = j0 + (2 * kc + half) * 8 + cb;
                        bool o0 = (j     <= r0g)     && (r0g - j     < SW);
                        bool o1 = (j + 1 <= r0g)     && (r0g - j - 1 < SW);
                        bool o2 = (j     <= r0g + 8) && (r0g + 8 - j < SW);
                        bool o3 = (j + 1 <= r0g + 8) && (r0g + 7 - j < SW);
                        float e0 = o0 ? ex2(sc[half][0]) : 0.0f;
                        float e1 = o1 ? ex2(sc[half][1]) : 0.0f;
                        float e2 = o2 ? ex2(sc[half][2]) : 0.0f;
                        float e3 = o3 ? ex2(sc[half][3]) : 0.0f;
                        lsum0 += e0 + e1; lsum1 += e2 + e3;
                        pe[2 * half]     = h2u(e0, e1);
                        pe[2 * half + 1] = h2u(e2, e3);
                    }
                }

#pragma unroll
                for (int dn = 0; dn < 8; dn++) {
                    uint32_t b[4];
                    uint32_t ad = vb +
                        (uint32_t)((kc * 16 + vbrow) * QSTR + dn * 16 + vbcol) * 2;
                    ldsm_x4_t(b, ad);
                    mma16816(o[2 * dn],     pe, b[0], b[1]);
                    mma16816(o[2 * dn + 1], pe, b[2], b[3]);
                }
            }
        }

        __syncthreads();                       // everyone done reading buf[t&1]
        int jn2 = j0 + 2 * BN;
        if (jn2 < qend) issue_tile(sb, t & 1, hkv, jn2, tid);
        CP_COMMIT();                           // one group per iter (may be empty)
        CP_WAIT1();                            // tile t+1 resident
        __syncthreads();
    }

    // ---- epilogue: row-sum reduce, add sink, normalize, store ----
    lsum0 += __shfl_xor_sync(0xFFFFFFFF, lsum0, 1);
    lsum0 += __shfl_xor_sync(0xFFFFFFFF, lsum0, 2);
    lsum1 += __shfl_xor_sync(0xFFFFFFFF, lsum1, 1);
    lsum1 += __shfl_xor_sync(0xFFFFFFFF, lsum1, 2);
    const float sexp = ex2(gsink[h] * L2E);
    const float inv0 = 1.0f / (lsum0 + sexp);
    const float inv1 = 1.0f / (lsum1 + sexp);

    const size_t ob0 = ((size_t)r0g * HQ + h) * DH;
    const size_t ob1 = ((size_t)(r0g + 8) * HQ + h) * DH;
#pragma unroll
    for (int nc = 0; nc < 16; nc++) {
        int d0 = nc * 8 + cb;
        float2 v0 = make_float2(o[nc][0] * inv0, o[nc][1] * inv0);
        float2 v1 = make_float2(o[nc][2] * inv1, o[nc][3] * inv1);
        *reinterpret_cast<float2*>(&gout[ob0 + d0]) = v0;
        *reinterpret_cast<float2*>(&gout[ob1 + d0]) = v1;
    }
}

extern "C" void kernel_launch(void* const* d_in, const int* in_sizes, int n_in,
                              void* d_out, int out_size)
{
    const float* q    = (const float*)d_in[0];
    const float* k    = (const float*)d_in[1];
    const float* v    = (const float*)d_in[2];
    const float* sink = (const float*)d_in[3];
    // d_in[4] cache_state, d_in[5] seq_block_ids: dead inputs (reference discards the write)
    float* out = (float*)d_out;

    cvt_kv<<<SEQ * HKV * 32 / 256, 256>>>(k, v);

    cudaFuncSetAttribute(attn_hmma, cudaFuncAttributeMaxDynamicSharedMemorySize, SM_TOTAL);
    dim3 grid(SEQ / BM, HQ);
    attn_hmma<<<grid, NT, SM_TOTAL>>>(q, sink, out);
}